// round 6
// baseline (speedup 1.0000x reference)
#include <cuda_runtime.h>

// HashTables: rolling xor-hash over prefix windows {1,2,4,...,128}, then gather
// 8 embedding rows (64 f32 each) per (b,t) into out[b][t][8*64].
//
// Proven-exact math (R2/R3): BUCKETS = 2^19 so h % BUCKETS == h & 0x7FFFF and
// only the low 32 bits of token*prime matter -> pure u32 arithmetic. Zero
// tokens XOR as no-ops, so the t-1-j < 0 boundary is a zero-padded smem halo.
//
// R5 -> R6: abandon cp.async.bulk (two failed rounds, race not localizable
// without a profile). Back to the 18.9us LDG/STG design, but gather phase is
// two-phase batched: 8 independent LDG.128 into a register array, then 8
// STG.128, twice. Doubles per-thread MLP and unchains stores from loads.
// Each thread's (table, f4-slot) is fixed; only the position varies.

#define T_LEN   4096
#define B_ROWS  8
#define P_TILE  32          // t-positions per block
#define NTHR    256
#define HALO    128
#define MASK19  0x7FFFFu

static __device__ __forceinline__ unsigned prime_of(int j) {
    const unsigned PR[8] = {2654435761u, 2246822519u, 3266489917u, 2028178513u,
                            1220703125u, 1610612741u, 805306457u, 402653189u};
    return PR[j & 7];
}

static __device__ __forceinline__ void stg_cs_f4(float4* p, float4 v) {
    asm volatile("st.global.cs.v4.f32 [%0], {%1, %2, %3, %4};"
                 :: "l"(p), "f"(v.x), "f"(v.y), "f"(v.z), "f"(v.w) : "memory");
}

__global__ __launch_bounds__(NTHR)
void hash_gather_kernel(const int* __restrict__ tokens,         // [B][T] int32
                        const float* __restrict__ tables,       // [8][2^19][64] f32
                        float* __restrict__ out)                // [B][T][512] f32
{
    __shared__ unsigned s_tok[P_TILE + HALO];   // 160 u32
    __shared__ unsigned s_idx[P_TILE * 8];      // bucket ids per (pos, table)

    const int tid = threadIdx.x;
    const int b  = blockIdx.y;
    const int t0 = blockIdx.x * P_TILE;

    // ---- Phase 0: stage tokens, zero-pad before row start ----
    if (tid < P_TILE + HALO) {
        int g = t0 - HALO + tid;
        s_tok[tid] = (g >= 0) ? (unsigned)tokens[(size_t)b * T_LEN + g] : 0u;
    }
    __syncthreads();

    // ---- Phase 1: rolling hash, snapshot at each power-of-two window ----
    if (tid < P_TILE) {
        unsigned h = 0;
        int w = 0;
        #pragma unroll
        for (int j = 0; j < 128; j++) {
            h ^= s_tok[tid + (HALO - 1) - j] * prime_of(j);
            const int off = j + 1;
            if ((off & (off - 1)) == 0) {       // off in {1,2,4,...,128}
                s_idx[tid * 8 + w] = h & MASK19;
                w++;
            }
        }
    }
    __syncthreads();

    // ---- Phase 2: gather + write, two-phase batched (8 loads, then 8 stores)
    // Thread handles a fixed (tbl, f4) slot across 16 positions p = p0 + 2k.
    // 16 consecutive threads cover one contiguous 256B table row; stores are
    // fully coalesced (contiguous 2KB per position).
    const int rest = tid & 127;         // within-position element
    const int tbl  = rest >> 4;         // table id 0..7
    const int f4   = rest & 15;         // float4 within 64-float row
    const int p0   = tid >> 7;          // 0 or 1

    const float4* __restrict__ tb =
        (const float4*)tables + ((size_t)tbl << 23) + f4;   // tbl*2^19 rows *16 f4
    float4* __restrict__ ob =
        (float4*)out + (((size_t)b * T_LEN + t0) << 7) + rest;

    #pragma unroll
    for (int half = 0; half < 2; half++) {
        float4 v[8];
        #pragma unroll
        for (int k = 0; k < 8; k++) {
            const int p = p0 + 2 * (half * 8 + k);
            v[k] = __ldg(tb + ((size_t)s_idx[p * 8 + tbl] << 4));
        }
        #pragma unroll
        for (int k = 0; k < 8; k++) {
            const int p = p0 + 2 * (half * 8 + k);
            stg_cs_f4(ob + ((size_t)p << 7), v[k]);
        }
    }
}

extern "C" void kernel_launch(void* const* d_in, const int* in_sizes, int n_in,
                              void* d_out, int out_size) {
    const int* tokens   = (const int*)d_in[0];
    const float* tables = (const float*)d_in[1];
    float* out          = (float*)d_out;

    dim3 grid(T_LEN / P_TILE, B_ROWS);   // (128, 8) = 1024 blocks
    hash_gather_kernel<<<grid, NTHR>>>(tokens, tables, out);
}